// round 11
// baseline (speedup 1.0000x reference)
#include <cuda_runtime.h>
#include <cstdint>
#include <cstddef>

// ---------------------------------------------------------------------------
// SNN forward:
//   GEMM1+pack: cur1 = data @ w1^T + b1 (double-buffered SIMT fp32, FFMA2;
//     R1-identical arithmetic) -> LIF1 pattern bytes, cur1 never stored.
//   tail v4 (256 thr, 2 cols/thread): deterministic counting sort by pattern
//     byte, run-sums with unroll-4 prefetched LDG.64 (MLP 4), one predicated
//     merge per bin; LIF2 + w3-dot + mean in-register -> out[b].
//   R8 ncu: tail occ=54.7% (reg-limited), issue=50.7% -> latency-bound;
//   this round doubles warps/row and quadruples per-thread MLP.
// ---------------------------------------------------------------------------

static constexpr int BB  = 16384;
static constexpr int DIN = 512;
static constexpr int H0  = 1024;
static constexpr int H1  = 512;
static constexpr int T   = 8;

// Scratch (device globals -- no runtime allocation allowed)
__device__ __align__(256) unsigned char g_pack[(size_t)BB * H0];  // 16 MB
__device__ __align__(256) float         g_w2t [(size_t)H0 * H1]; //  2 MB

// ===========================================================================
// GEMM1 + fused LIF1 pack (R10 verbatim -- bit-identical cur1/pack bytes)
// ===========================================================================
__global__ void __launch_bounds__(256) sgemm1_pack_kernel(
    const float* __restrict__ A,
    const float* __restrict__ W,
    const float* __restrict__ bias,
    unsigned char* __restrict__ pack,
    int M, int N, int K)
{
    __shared__ float As[2][16][128];
    __shared__ float Bs[2][16][128];

    const int tx = threadIdx.x;
    const int tm = tx >> 4;
    const int tn = tx & 15;

    const int m0 = blockIdx.y * 128;
    const int n0 = blockIdx.x * 128;

    const int f0 = tx;
    const int f1 = tx + 256;
    const int r0 = f0 >> 2, c40 = (f0 & 3) * 4;
    const int r1 = f1 >> 2, c41 = (f1 & 3) * 4;

    unsigned long long acc2[8][4];
#pragma unroll
    for (int i = 0; i < 8; ++i)
#pragma unroll
        for (int j = 0; j < 4; ++j) acc2[i][j] = 0ull;

    float4 ra0, ra1, rb0, rb1;

    auto load_regs = [&](int kt) {
        ra0 = *reinterpret_cast<const float4*>(&A[(size_t)(m0 + r0) * K + kt + c40]);
        ra1 = *reinterpret_cast<const float4*>(&A[(size_t)(m0 + r1) * K + kt + c41]);
        rb0 = *reinterpret_cast<const float4*>(&W[(size_t)(n0 + r0) * K + kt + c40]);
        rb1 = *reinterpret_cast<const float4*>(&W[(size_t)(n0 + r1) * K + kt + c41]);
    };
    auto store_smem = [&](int buf) {
        As[buf][c40 + 0][r0] = ra0.x;
        As[buf][c40 + 1][r0] = ra0.y;
        As[buf][c40 + 2][r0] = ra0.z;
        As[buf][c40 + 3][r0] = ra0.w;
        As[buf][c41 + 0][r1] = ra1.x;
        As[buf][c41 + 1][r1] = ra1.y;
        As[buf][c41 + 2][r1] = ra1.z;
        As[buf][c41 + 3][r1] = ra1.w;
        Bs[buf][c40 + 0][r0] = rb0.x;
        Bs[buf][c40 + 1][r0] = rb0.y;
        Bs[buf][c40 + 2][r0] = rb0.z;
        Bs[buf][c40 + 3][r0] = rb0.w;
        Bs[buf][c41 + 0][r1] = rb1.x;
        Bs[buf][c41 + 1][r1] = rb1.y;
        Bs[buf][c41 + 2][r1] = rb1.z;
        Bs[buf][c41 + 3][r1] = rb1.w;
    };

    load_regs(0);
    store_smem(0);
    __syncthreads();

    const int nt = K / 16;
    for (int it = 0; it < nt; ++it) {
        const int buf = it & 1;
        const bool more = (it + 1 < nt);
        if (more) load_regs((it + 1) * 16);

#pragma unroll
        for (int k = 0; k < 16; ++k) {
            float a[8];
            unsigned long long b2[4];
            *reinterpret_cast<float4*>(&a[0]) =
                *reinterpret_cast<const float4*>(&As[buf][k][tm * 8]);
            *reinterpret_cast<float4*>(&a[4]) =
                *reinterpret_cast<const float4*>(&As[buf][k][tm * 8 + 4]);
            *reinterpret_cast<float4*>(&b2[0]) =
                *reinterpret_cast<const float4*>(&Bs[buf][k][tn * 8]);
            *reinterpret_cast<float4*>(&b2[2]) =
                *reinterpret_cast<const float4*>(&Bs[buf][k][tn * 8 + 4]);
#pragma unroll
            for (int i = 0; i < 8; ++i) {
                unsigned long long a2;
                asm("mov.b64 %0, {%1, %1};" : "=l"(a2) : "f"(a[i]));
#pragma unroll
                for (int j = 0; j < 4; ++j)
                    asm("fma.rn.f32x2 %0, %1, %2, %0;"
                        : "+l"(acc2[i][j]) : "l"(a2), "l"(b2[j]));
            }
        }

        if (more) {
            store_smem(buf ^ 1);
            __syncthreads();
        }
    }

    float bj[8];
    const int gn0 = n0 + tn * 8;
#pragma unroll
    for (int j = 0; j < 8; ++j) bj[j] = __ldg(&bias[gn0 + j]);

#pragma unroll
    for (int i = 0; i < 8; ++i) {
        const int gm = m0 + tm * 8 + i;
        float accf[8];
#pragma unroll
        for (int j = 0; j < 4; ++j)
            asm("mov.b64 {%0, %1}, %2;"
                : "=f"(accf[2 * j]), "=f"(accf[2 * j + 1]) : "l"(acc2[i][j]));

        unsigned long long u = 0ull;
#pragma unroll
        for (int j = 0; j < 8; ++j) {
            const float c = accf[j] + bj[j];
            float mem = 0.0f;
            unsigned p = 0;
#pragma unroll
            for (int t = 0; t < T; ++t) {
                const float reset = (mem > 1.0f) ? 1.0f : 0.0f;   // OLD mem
                mem = mem + c - reset;                             // beta1 = 1.0
                p |= ((mem - 1.0f) > 0.0f ? 1u : 0u) << t;
            }
            u |= (unsigned long long)p << (8 * j);
        }
        *reinterpret_cast<unsigned long long*>(&pack[(size_t)gm * N + gn0]) = u;
    }
}

// ===========================================================================
// Transpose w2 [H1][H0] -> w2t [H0][H1]
// ===========================================================================
__global__ void transpose_w2_kernel(const float* __restrict__ w2,
                                    float* __restrict__ w2t)
{
    __shared__ float tile[32][33];
    const int bx = blockIdx.x * 32;
    const int by = blockIdx.y * 32;
    const int tx = threadIdx.x, ty = threadIdx.y;
#pragma unroll
    for (int j = 0; j < 32; j += 8)
        tile[ty + j][tx] = w2[(size_t)(by + ty + j) * H0 + bx + tx];
    __syncthreads();
#pragma unroll
    for (int j = 0; j < 32; j += 8)
        w2t[(size_t)(bx + ty + j) * H1 + by + tx] = tile[tx][ty + j];
}

// ===========================================================================
// Fused tail v4: 256 threads, thread owns 2 cols (n0 = tid*2).
//   binning: 1 pattern per thread, 8-warp scans, per-warp cursors (ordering
//   deterministic); run-sums with unroll-4 prefetch; per-bin predicated merge.
// ===========================================================================
__global__ void __launch_bounds__(256) snn_tail_kernel(
    const unsigned char* __restrict__ pack,   // [BB][H0]
    const float* __restrict__ w2t,            // [H0][H1]
    const float* __restrict__ b2,
    const float* __restrict__ w3,
    const float* __restrict__ b3,
    float* __restrict__ out)
{
    __shared__ uint16_t s_idx[H0];
    __shared__ int      s_cnt[256];
    __shared__ int      s_start[256];
    __shared__ int      s_wbase[8][256];
    __shared__ int      s_binlist[256];
    __shared__ int      s_w8a[8], s_w8b[8];
    __shared__ int      s_nbins;
    __shared__ float    s_red[8];

    const int b    = blockIdx.x;
    const int tid  = threadIdx.x;
    const int lane = tid & 31;
    const int wid  = tid >> 5;
    const unsigned FULL = 0xFFFFFFFFu;

    // ---- load pattern bytes (thread owns i = tid*4 .. tid*4+3) ----
    const uint32_t word =
        reinterpret_cast<const uint32_t*>(pack)[(size_t)b * (H0 / 4) + tid];
    uint32_t bytes[4];
#pragma unroll
    for (int j = 0; j < 4; ++j) bytes[j] = (word >> (8 * j)) & 255u;

    // ---- zero per-warp histogram (8 x 256) ----
#pragma unroll
    for (int k = 0; k < 8; ++k) {
        const int e = tid * 8 + k;
        s_wbase[e >> 8][e & 255] = 0;
    }
    __syncthreads();

    // ---- per-warp histogram (zeros excluded) ----
#pragma unroll
    for (int j = 0; j < 4; ++j)
        if (bytes[j]) atomicAdd(&s_wbase[wid][bytes[j]], 1);
    __syncthreads();

    // ---- totals: thread owns pattern p = tid ----
    const int p = tid;
    int v = 0;
#pragma unroll
    for (int w = 0; w < 8; ++w) v += s_wbase[w][p];

    // ---- exclusive scan over 256 counts ----
    {
        int inc = v;
#pragma unroll
        for (int d = 1; d < 32; d <<= 1) {
            const int t = __shfl_up_sync(FULL, inc, d);
            if (lane >= d) inc += t;
        }
        if (lane == 31) s_w8a[wid] = inc;
        __syncthreads();
        int woff = 0;
#pragma unroll
        for (int w = 0; w < 8; ++w) woff += (w < wid) ? s_w8a[w] : 0;
        s_start[p] = woff + inc - v;
        s_cnt[p]   = v;
    }

    // ---- compact nonempty pattern list (exclude pattern 0) ----
    {
        const int f = (p != 0 && v > 0) ? 1 : 0;
        int inc = f;
#pragma unroll
        for (int d = 1; d < 32; d <<= 1) {
            const int t = __shfl_up_sync(FULL, inc, d);
            if (lane >= d) inc += t;
        }
        if (lane == 31) s_w8b[wid] = inc;
        __syncthreads();
        int woff = 0;
#pragma unroll
        for (int w = 0; w < 8; ++w) woff += (w < wid) ? s_w8b[w] : 0;
        const int c0 = woff + inc - f;
        if (f) s_binlist[c0] = p;
        if (tid == 255) s_nbins = c0 + f;
    }
    __syncthreads();

    // ---- convert histogram to per-warp cursors ----
    {
        int run = s_start[p];
#pragma unroll
        for (int w = 0; w < 8; ++w) {
            const int t = s_wbase[w][p];
            s_wbase[w][p] = run;
            run += t;
        }
    }
    __syncthreads();

    // ---- deterministic scatter: slot-sequential, per-warp cursors ----
#pragma unroll
    for (int j = 0; j < 4; ++j) {
        const uint32_t bj = bytes[j];
        const uint32_t grp = __match_any_sync(FULL, bj);
        const int leader = __ffs(grp) - 1;
        int base = 0;
        if (bj && lane == leader)
            base = atomicAdd(&s_wbase[wid][bj], __popc(grp));
        base = __shfl_sync(FULL, base, leader);
        if (bj) {
            const int pos = base + __popc(grp & ((1u << lane) - 1u));
            s_idx[pos] = (uint16_t)(tid * 4 + j);
        }
    }
    __syncthreads();

    // ---- run-hoisted sparse accumulation (2 cols/thread, MLP-4 prefetch) --
    unsigned long long acc[T];
#pragma unroll
    for (int t = 0; t < T; ++t) acc[t] = 0ull;

    const char* wbase = reinterpret_cast<const char*>(w2t) + tid * 8;
    const int nbins = s_nbins;

    for (int bi = 0; bi < nbins; ++bi) {
        const int pp = s_binlist[bi];
        const int st = s_start[pp];
        const int en = st + s_cnt[pp];

        unsigned long long rs = 0ull;
        int k = st;
        for (; k + 4 <= en; k += 4) {
            const uint32_t i0 = s_idx[k];
            const uint32_t i1 = s_idx[k + 1];
            const uint32_t i2 = s_idx[k + 2];
            const uint32_t i3 = s_idx[k + 3];
            unsigned long long a0, a1, a2, a3;
            asm("ld.global.nc.L1::evict_last.u64 %0, [%1];"
                : "=l"(a0) : "l"(wbase + (size_t)i0 * (H1 * 4)));
            asm("ld.global.nc.L1::evict_last.u64 %0, [%1];"
                : "=l"(a1) : "l"(wbase + (size_t)i1 * (H1 * 4)));
            asm("ld.global.nc.L1::evict_last.u64 %0, [%1];"
                : "=l"(a2) : "l"(wbase + (size_t)i2 * (H1 * 4)));
            asm("ld.global.nc.L1::evict_last.u64 %0, [%1];"
                : "=l"(a3) : "l"(wbase + (size_t)i3 * (H1 * 4)));
            asm("add.rn.f32x2 %0, %0, %1;" : "+l"(rs) : "l"(a0));
            asm("add.rn.f32x2 %0, %0, %1;" : "+l"(rs) : "l"(a1));
            asm("add.rn.f32x2 %0, %0, %1;" : "+l"(rs) : "l"(a2));
            asm("add.rn.f32x2 %0, %0, %1;" : "+l"(rs) : "l"(a3));
        }
        for (; k < en; ++k) {
            const uint32_t i = s_idx[k];
            unsigned long long a0;
            asm("ld.global.nc.L1::evict_last.u64 %0, [%1];"
                : "=l"(a0) : "l"(wbase + (size_t)i * (H1 * 4)));
            asm("add.rn.f32x2 %0, %0, %1;" : "+l"(rs) : "l"(a0));
        }

        // merge run-sum into per-t accumulators (bits of pp)
#pragma unroll
        for (int t = 0; t < T; ++t) {
            asm("{ .reg .pred q;\n\t"
                "setp.ne.u32 q, %2, 0;\n\t"
                "@q add.rn.f32x2 %0, %0, %1; }"
                : "+l"(acc[t])
                : "l"(rs), "r"((unsigned)pp & (1u << t)));
        }
    }

    // ---- LIF2 + output head (thread owns n0, n0+1) ----
    const int n0 = tid * 2;
    const float2 b2v = *reinterpret_cast<const float2*>(b2 + n0);
    const float2 w3v = *reinterpret_cast<const float2*>(w3 + n0);
    float m0 = 0.0f, m1 = 0.0f, aout = 0.0f;
#pragma unroll
    for (int t = 0; t < T; ++t) {
        float a0, a1;
        asm("mov.b64 {%0, %1}, %2;" : "=f"(a0), "=f"(a1) : "l"(acc[t]));
        const float c0 = a0 + b2v.x;
        const float c1 = a1 + b2v.y;
        const float r0 = (m0 > 1.0f) ? 1.0f : 0.0f;   // reset on OLD mem
        const float r1 = (m1 > 1.0f) ? 1.0f : 0.0f;
        m0 = 0.95f * m0 + c0 - r0;
        m1 = 0.95f * m1 + c1 - r1;
        aout += ((m0 - 1.0f) > 0.0f) ? w3v.x : 0.0f;
        aout += ((m1 - 1.0f) > 0.0f) ? w3v.y : 0.0f;
    }

    // block reduce (256 threads)
#pragma unroll
    for (int d = 16; d > 0; d >>= 1)
        aout += __shfl_down_sync(FULL, aout, d);
    if (lane == 0) s_red[wid] = aout;
    __syncthreads();
    if (tid == 0) {
        float s = 0.0f;
#pragma unroll
        for (int k = 0; k < 8; ++k) s += s_red[k];
        out[b] = s * (1.0f / T) + __ldg(&b3[0]);
    }
}

// ---------------------------------------------------------------------------
extern "C" void kernel_launch(void* const* d_in, const int* in_sizes, int n_in,
                              void* d_out, int out_size)
{
    const float* data = (const float*)d_in[0];
    const float* w1   = (const float*)d_in[1];
    const float* b1   = (const float*)d_in[2];
    const float* w2   = (const float*)d_in[3];
    const float* b2   = (const float*)d_in[4];
    const float* w3   = (const float*)d_in[5];
    const float* b3   = (const float*)d_in[6];
    float* out = (float*)d_out;

    unsigned char* pack;
    float* w2t;
    cudaGetSymbolAddress((void**)&pack, g_pack);
    cudaGetSymbolAddress((void**)&w2t,  g_w2t);

    // 1) transpose w2 -> w2t [H0][H1]
    {
        dim3 grid(H0 / 32, H1 / 32);     // (32, 16)
        transpose_w2_kernel<<<grid, dim3(32, 8)>>>(w2, w2t);
    }

    // 2) GEMM1 + fused LIF1 pack (cur1 never materialized)
    {
        dim3 grid(H0 / 128, BB / 128);   // (8, 128)
        sgemm1_pack_kernel<<<grid, 256>>>(data, w1, b1, pack, BB, H0, DIN);
    }

    // 3) fused sparse layer-2 + LIF2 + output head
    snn_tail_kernel<<<BB, 256>>>(pack, w2t, b2, w3, b3, out);
}

// round 12
// speedup vs baseline: 1.1228x; 1.1228x over previous
#include <cuda_runtime.h>
#include <cstdint>
#include <cstddef>

// ---------------------------------------------------------------------------
// SNN forward:
//   GEMM1+pack: cur1 = data @ w1^T + b1 (double-buffered SIMT fp32, FFMA2;
//     R1-identical arithmetic) -> LIF1 pattern bytes, cur1 never stored.
//   tail v5 = R8 structure (128 thr, 4 cols/thread, LDG.128) + unroll-4
//     prefetch in the bin loop (R8 ncu: issue=50.7%, latency-exposed;
//     R11 showed the 256-thr restructure was the regression, not the MLP).
//   Numerics: rs add order preserved (k-ascending) -> bit-identical output.
// ---------------------------------------------------------------------------

static constexpr int BB  = 16384;
static constexpr int DIN = 512;
static constexpr int H0  = 1024;
static constexpr int H1  = 512;
static constexpr int T   = 8;

// Scratch (device globals -- no runtime allocation allowed)
__device__ __align__(256) unsigned char g_pack[(size_t)BB * H0];  // 16 MB
__device__ __align__(256) float         g_w2t [(size_t)H0 * H1]; //  2 MB

// ===========================================================================
// GEMM1 + fused LIF1 pack (R10 verbatim -- bit-identical cur1/pack bytes)
// ===========================================================================
__global__ void __launch_bounds__(256) sgemm1_pack_kernel(
    const float* __restrict__ A,
    const float* __restrict__ W,
    const float* __restrict__ bias,
    unsigned char* __restrict__ pack,
    int M, int N, int K)
{
    __shared__ float As[2][16][128];
    __shared__ float Bs[2][16][128];

    const int tx = threadIdx.x;
    const int tm = tx >> 4;
    const int tn = tx & 15;

    const int m0 = blockIdx.y * 128;
    const int n0 = blockIdx.x * 128;

    const int f0 = tx;
    const int f1 = tx + 256;
    const int r0 = f0 >> 2, c40 = (f0 & 3) * 4;
    const int r1 = f1 >> 2, c41 = (f1 & 3) * 4;

    unsigned long long acc2[8][4];
#pragma unroll
    for (int i = 0; i < 8; ++i)
#pragma unroll
        for (int j = 0; j < 4; ++j) acc2[i][j] = 0ull;

    float4 ra0, ra1, rb0, rb1;

    auto load_regs = [&](int kt) {
        ra0 = *reinterpret_cast<const float4*>(&A[(size_t)(m0 + r0) * K + kt + c40]);
        ra1 = *reinterpret_cast<const float4*>(&A[(size_t)(m0 + r1) * K + kt + c41]);
        rb0 = *reinterpret_cast<const float4*>(&W[(size_t)(n0 + r0) * K + kt + c40]);
        rb1 = *reinterpret_cast<const float4*>(&W[(size_t)(n0 + r1) * K + kt + c41]);
    };
    auto store_smem = [&](int buf) {
        As[buf][c40 + 0][r0] = ra0.x;
        As[buf][c40 + 1][r0] = ra0.y;
        As[buf][c40 + 2][r0] = ra0.z;
        As[buf][c40 + 3][r0] = ra0.w;
        As[buf][c41 + 0][r1] = ra1.x;
        As[buf][c41 + 1][r1] = ra1.y;
        As[buf][c41 + 2][r1] = ra1.z;
        As[buf][c41 + 3][r1] = ra1.w;
        Bs[buf][c40 + 0][r0] = rb0.x;
        Bs[buf][c40 + 1][r0] = rb0.y;
        Bs[buf][c40 + 2][r0] = rb0.z;
        Bs[buf][c40 + 3][r0] = rb0.w;
        Bs[buf][c41 + 0][r1] = rb1.x;
        Bs[buf][c41 + 1][r1] = rb1.y;
        Bs[buf][c41 + 2][r1] = rb1.z;
        Bs[buf][c41 + 3][r1] = rb1.w;
    };

    load_regs(0);
    store_smem(0);
    __syncthreads();

    const int nt = K / 16;
    for (int it = 0; it < nt; ++it) {
        const int buf = it & 1;
        const bool more = (it + 1 < nt);
        if (more) load_regs((it + 1) * 16);

#pragma unroll
        for (int k = 0; k < 16; ++k) {
            float a[8];
            unsigned long long b2[4];
            *reinterpret_cast<float4*>(&a[0]) =
                *reinterpret_cast<const float4*>(&As[buf][k][tm * 8]);
            *reinterpret_cast<float4*>(&a[4]) =
                *reinterpret_cast<const float4*>(&As[buf][k][tm * 8 + 4]);
            *reinterpret_cast<float4*>(&b2[0]) =
                *reinterpret_cast<const float4*>(&Bs[buf][k][tn * 8]);
            *reinterpret_cast<float4*>(&b2[2]) =
                *reinterpret_cast<const float4*>(&Bs[buf][k][tn * 8 + 4]);
#pragma unroll
            for (int i = 0; i < 8; ++i) {
                unsigned long long a2;
                asm("mov.b64 %0, {%1, %1};" : "=l"(a2) : "f"(a[i]));
#pragma unroll
                for (int j = 0; j < 4; ++j)
                    asm("fma.rn.f32x2 %0, %1, %2, %0;"
                        : "+l"(acc2[i][j]) : "l"(a2), "l"(b2[j]));
            }
        }

        if (more) {
            store_smem(buf ^ 1);
            __syncthreads();
        }
    }

    float bj[8];
    const int gn0 = n0 + tn * 8;
#pragma unroll
    for (int j = 0; j < 8; ++j) bj[j] = __ldg(&bias[gn0 + j]);

#pragma unroll
    for (int i = 0; i < 8; ++i) {
        const int gm = m0 + tm * 8 + i;
        float accf[8];
#pragma unroll
        for (int j = 0; j < 4; ++j)
            asm("mov.b64 {%0, %1}, %2;"
                : "=f"(accf[2 * j]), "=f"(accf[2 * j + 1]) : "l"(acc2[i][j]));

        unsigned long long u = 0ull;
#pragma unroll
        for (int j = 0; j < 8; ++j) {
            const float c = accf[j] + bj[j];
            float mem = 0.0f;
            unsigned p = 0;
#pragma unroll
            for (int t = 0; t < T; ++t) {
                const float reset = (mem > 1.0f) ? 1.0f : 0.0f;   // OLD mem
                mem = mem + c - reset;                             // beta1 = 1.0
                p |= ((mem - 1.0f) > 0.0f ? 1u : 0u) << t;
            }
            u |= (unsigned long long)p << (8 * j);
        }
        *reinterpret_cast<unsigned long long*>(&pack[(size_t)gm * N + gn0]) = u;
    }
}

// ===========================================================================
// Transpose w2 [H1][H0] -> w2t [H0][H1]
// ===========================================================================
__global__ void transpose_w2_kernel(const float* __restrict__ w2,
                                    float* __restrict__ w2t)
{
    __shared__ float tile[32][33];
    const int bx = blockIdx.x * 32;
    const int by = blockIdx.y * 32;
    const int tx = threadIdx.x, ty = threadIdx.y;
#pragma unroll
    for (int j = 0; j < 32; j += 8)
        tile[ty + j][tx] = w2[(size_t)(by + ty + j) * H0 + bx + tx];
    __syncthreads();
#pragma unroll
    for (int j = 0; j < 32; j += 8)
        w2t[(size_t)(bx + ty + j) * H1 + by + tx] = tile[tx][ty + j];
}

// ===========================================================================
// Fused tail v5: 128 threads, thread owns 4 cols (n0 = tid*4), LDG.128.
// Binning identical to R8/R9/R10; bin loop now unroll-4 prefetched (MLP 4),
// with adds kept in strict k order (bit-identical run sums).
// ===========================================================================
__global__ void __launch_bounds__(128) snn_tail_kernel(
    const unsigned char* __restrict__ pack,   // [BB][H0]
    const float* __restrict__ w2t,            // [H0][H1]
    const float* __restrict__ b2,
    const float* __restrict__ w3,
    const float* __restrict__ b3,
    float* __restrict__ out)
{
    __shared__ uint16_t s_idx[H0];
    __shared__ int      s_cnt[256];
    __shared__ int      s_start[256];
    __shared__ int      s_wbase[4][256];
    __shared__ int      s_binlist[256];
    __shared__ int      s_w4a[4], s_w4b[4];
    __shared__ int      s_nbins;
    __shared__ float    s_red[4];

    const int b    = blockIdx.x;
    const int tid  = threadIdx.x;
    const int lane = tid & 31;
    const int wid  = tid >> 5;
    const unsigned FULL = 0xFFFFFFFFu;

    const uint2 wd =
        reinterpret_cast<const uint2*>(pack)[(size_t)b * (H0 / 8) + tid];
    uint32_t bytes[8];
#pragma unroll
    for (int j = 0; j < 4; ++j) {
        bytes[j]     = (wd.x >> (8 * j)) & 255u;
        bytes[4 + j] = (wd.y >> (8 * j)) & 255u;
    }

#pragma unroll
    for (int k = 0; k < 8; ++k) s_wbase[(tid * 8 + k) >> 8][(tid * 8 + k) & 255] = 0;
    __syncthreads();

#pragma unroll
    for (int j = 0; j < 8; ++j)
        if (bytes[j]) atomicAdd(&s_wbase[wid][bytes[j]], 1);
    __syncthreads();

    const int p0 = tid * 2, p1 = tid * 2 + 1;
    const int v0 = s_wbase[0][p0] + s_wbase[1][p0] + s_wbase[2][p0] + s_wbase[3][p0];
    const int v1 = s_wbase[0][p1] + s_wbase[1][p1] + s_wbase[2][p1] + s_wbase[3][p1];

    {
        int inc = v0 + v1;
#pragma unroll
        for (int d = 1; d < 32; d <<= 1) {
            const int t = __shfl_up_sync(FULL, inc, d);
            if (lane >= d) inc += t;
        }
        if (lane == 31) s_w4a[wid] = inc;
        __syncthreads();
        int woff = 0;
#pragma unroll
        for (int w = 0; w < 4; ++w) woff += (w < wid) ? s_w4a[w] : 0;
        const int e0 = woff + inc - (v0 + v1);
        s_start[p0] = e0;
        s_start[p1] = e0 + v0;
        s_cnt[p0] = v0;
        s_cnt[p1] = v1;
    }

    {
        const int f0 = (p0 != 0 && v0 > 0) ? 1 : 0;
        const int f1 = (v1 > 0) ? 1 : 0;
        int inc = f0 + f1;
#pragma unroll
        for (int d = 1; d < 32; d <<= 1) {
            const int t = __shfl_up_sync(FULL, inc, d);
            if (lane >= d) inc += t;
        }
        if (lane == 31) s_w4b[wid] = inc;
        __syncthreads();
        int woff = 0;
#pragma unroll
        for (int w = 0; w < 4; ++w) woff += (w < wid) ? s_w4b[w] : 0;
        const int c0 = woff + inc - (f0 + f1);
        if (f0) s_binlist[c0] = p0;
        if (f1) s_binlist[c0 + f0] = p1;
        if (tid == 127) s_nbins = c0 + f0 + f1;
    }
    __syncthreads();

    {
#pragma unroll
        for (int pp = 0; pp < 2; ++pp) {
            const int p = tid * 2 + pp;
            int run = s_start[p];
#pragma unroll
            for (int w = 0; w < 4; ++w) {
                const int t = s_wbase[w][p];
                s_wbase[w][p] = run;
                run += t;
            }
        }
    }
    __syncthreads();

#pragma unroll
    for (int j = 0; j < 8; ++j) {
        const uint32_t bj = bytes[j];
        const uint32_t grp = __match_any_sync(FULL, bj);
        const int leader = __ffs(grp) - 1;
        int base = 0;
        if (bj && lane == leader)
            base = atomicAdd(&s_wbase[wid][bj], __popc(grp));
        base = __shfl_sync(FULL, base, leader);
        if (bj) {
            const int pos = base + __popc(grp & ((1u << lane) - 1u));
            s_idx[pos] = (uint16_t)(tid * 8 + j);
        }
    }
    __syncthreads();

    unsigned long long acc[T][2];
#pragma unroll
    for (int t = 0; t < T; ++t) { acc[t][0] = 0ull; acc[t][1] = 0ull; }

    const char* wbase = reinterpret_cast<const char*>(w2t) + tid * 16;
    const int nbins = s_nbins;

    for (int bi = 0; bi < nbins; ++bi) {
        const int p  = s_binlist[bi];
        const int st = s_start[p];
        const int en = st + s_cnt[p];

        unsigned long long rs0 = 0ull, rs1 = 0ull;
        int k = st;
        // unroll-4: 4 independent LDG.128 in flight, adds in strict k order
        for (; k + 4 <= en; k += 4) {
            const uint32_t i0 = s_idx[k];
            const uint32_t i1 = s_idx[k + 1];
            const uint32_t i2 = s_idx[k + 2];
            const uint32_t i3 = s_idx[k + 3];
            unsigned long long a0, b0, a1, b1, a2, b2, a3, b3;
            asm("ld.global.nc.L1::evict_last.v2.u64 {%0, %1}, [%2];"
                : "=l"(a0), "=l"(b0) : "l"(wbase + (size_t)i0 * (H1 * 4)));
            asm("ld.global.nc.L1::evict_last.v2.u64 {%0, %1}, [%2];"
                : "=l"(a1), "=l"(b1) : "l"(wbase + (size_t)i1 * (H1 * 4)));
            asm("ld.global.nc.L1::evict_last.v2.u64 {%0, %1}, [%2];"
                : "=l"(a2), "=l"(b2) : "l"(wbase + (size_t)i2 * (H1 * 4)));
            asm("ld.global.nc.L1::evict_last.v2.u64 {%0, %1}, [%2];"
                : "=l"(a3), "=l"(b3) : "l"(wbase + (size_t)i3 * (H1 * 4)));
            asm("add.rn.f32x2 %0, %0, %1;" : "+l"(rs0) : "l"(a0));
            asm("add.rn.f32x2 %0, %0, %1;" : "+l"(rs1) : "l"(b0));
            asm("add.rn.f32x2 %0, %0, %1;" : "+l"(rs0) : "l"(a1));
            asm("add.rn.f32x2 %0, %0, %1;" : "+l"(rs1) : "l"(b1));
            asm("add.rn.f32x2 %0, %0, %1;" : "+l"(rs0) : "l"(a2));
            asm("add.rn.f32x2 %0, %0, %1;" : "+l"(rs1) : "l"(b2));
            asm("add.rn.f32x2 %0, %0, %1;" : "+l"(rs0) : "l"(a3));
            asm("add.rn.f32x2 %0, %0, %1;" : "+l"(rs1) : "l"(b3));
        }
        for (; k < en; ++k) {
            const uint32_t i = s_idx[k];
            unsigned long long w01, w23;
            asm("ld.global.nc.L1::evict_last.v2.u64 {%0, %1}, [%2];"
                : "=l"(w01), "=l"(w23)
                : "l"(wbase + (size_t)i * (H1 * 4)));
            asm("add.rn.f32x2 %0, %0, %1;" : "+l"(rs0) : "l"(w01));
            asm("add.rn.f32x2 %0, %0, %1;" : "+l"(rs1) : "l"(w23));
        }

#pragma unroll
        for (int t = 0; t < T; ++t) {
            asm("{ .reg .pred q;\n\t"
                "setp.ne.u32 q, %4, 0;\n\t"
                "@q add.rn.f32x2 %0, %0, %2;\n\t"
                "@q add.rn.f32x2 %1, %1, %3; }"
                : "+l"(acc[t][0]), "+l"(acc[t][1])
                : "l"(rs0), "l"(rs1), "r"((unsigned)p & (1u << t)));
        }
    }

    const int n0 = tid * 4;
    const float4 b2v = *reinterpret_cast<const float4*>(b2 + n0);
    const float4 w3v = *reinterpret_cast<const float4*>(w3 + n0);
    float m0 = 0.0f, m1 = 0.0f, m2 = 0.0f, m3 = 0.0f, aout = 0.0f;
#pragma unroll
    for (int t = 0; t < T; ++t) {
        float a0, a1, a2, a3;
        asm("mov.b64 {%0, %1}, %2;" : "=f"(a0), "=f"(a1) : "l"(acc[t][0]));
        asm("mov.b64 {%0, %1}, %2;" : "=f"(a2), "=f"(a3) : "l"(acc[t][1]));
        const float c0 = a0 + b2v.x, c1 = a1 + b2v.y;
        const float c2 = a2 + b2v.z, c3 = a3 + b2v.w;
        const float r0 = (m0 > 1.0f) ? 1.0f : 0.0f;   // reset on OLD mem
        const float r1 = (m1 > 1.0f) ? 1.0f : 0.0f;
        const float r2 = (m2 > 1.0f) ? 1.0f : 0.0f;
        const float r3 = (m3 > 1.0f) ? 1.0f : 0.0f;
        m0 = 0.95f * m0 + c0 - r0;
        m1 = 0.95f * m1 + c1 - r1;
        m2 = 0.95f * m2 + c2 - r2;
        m3 = 0.95f * m3 + c3 - r3;
        aout += ((m0 - 1.0f) > 0.0f) ? w3v.x : 0.0f;
        aout += ((m1 - 1.0f) > 0.0f) ? w3v.y : 0.0f;
        aout += ((m2 - 1.0f) > 0.0f) ? w3v.z : 0.0f;
        aout += ((m3 - 1.0f) > 0.0f) ? w3v.w : 0.0f;
    }

#pragma unroll
    for (int d = 16; d > 0; d >>= 1)
        aout += __shfl_down_sync(FULL, aout, d);
    if (lane == 0) s_red[wid] = aout;
    __syncthreads();
    if (tid == 0) {
        out[b] = (s_red[0] + s_red[1] + s_red[2] + s_red[3]) * (1.0f / T)
               + __ldg(&b3[0]);
    }
}

// ---------------------------------------------------------------------------
extern "C" void kernel_launch(void* const* d_in, const int* in_sizes, int n_in,
                              void* d_out, int out_size)
{
    const float* data = (const float*)d_in[0];
    const float* w1   = (const float*)d_in[1];
    const float* b1   = (const float*)d_in[2];
    const float* w2   = (const float*)d_in[3];
    const float* b2   = (const float*)d_in[4];
    const float* w3   = (const float*)d_in[5];
    const float* b3   = (const float*)d_in[6];
    float* out = (float*)d_out;

    unsigned char* pack;
    float* w2t;
    cudaGetSymbolAddress((void**)&pack, g_pack);
    cudaGetSymbolAddress((void**)&w2t,  g_w2t);

    // 1) transpose w2 -> w2t [H0][H1]
    {
        dim3 grid(H0 / 32, H1 / 32);     // (32, 16)
        transpose_w2_kernel<<<grid, dim3(32, 8)>>>(w2, w2t);
    }

    // 2) GEMM1 + fused LIF1 pack (cur1 never materialized)
    {
        dim3 grid(H0 / 128, BB / 128);   // (8, 128)
        sgemm1_pack_kernel<<<grid, 256>>>(data, w1, b1, pack, BB, H0, DIN);
    }

    // 3) fused sparse layer-2 + LIF2 + output head
    snn_tail_kernel<<<BB, 128>>>(pack, w2t, b2, w3, b3, out);
}